// round 5
// baseline (speedup 1.0000x reference)
#include <cuda_runtime.h>
#include <cuda_fp16.h>

#define N_MAX   100000
#define E_MAX   1600000
#define NFEAT   128
#define NHID    64
#define NCLS    40

// ---------------- device scratch (allocation-free) ----------------
__device__ int   g_is64;
__device__ int   g_src[E_MAX];
__device__ int   g_dst[E_MAX];
__device__ int   g_csr[E_MAX];
__device__ int   g_deg[N_MAX];
__device__ int   g_off[N_MAX];
__device__ int   g_cur[N_MAX];
__device__ unsigned long long g_part[512];            // lookback (valid<<32)|sum
__device__ __align__(16) uint4    g_h1h[N_MAX * 8];   // h1  [N,64] fp16
__device__ __align__(16) uint4    g_a1h[N_MAX * 8];   // agg1[N,64] fp16 (REDG)
__device__ __align__(16) unsigned g_h2h[N_MAX * 20];  // h2  [N,40] fp16

// ---------------- pre: zero deg + lookback flags + dtype detect -----
__global__ void k_pre(const unsigned* __restrict__ ei, int n) {
    int i = blockIdx.x * blockDim.x + threadIdx.x;
    if (i < n) g_deg[i] = 0;
    if (i < 512) g_part[i] = 0ULL;
    if (i == 0) {
        unsigned hi = 0;
        #pragma unroll
        for (int j = 1; j < 64; j += 2) hi |= ei[j];
        g_is64 = (hi == 0u) ? 1 : 0;
    }
}

// ------- hist: edges -> int32 + degree histogram (4 edges/thread) ----
__global__ void k_hist(const void* __restrict__ ei, int E) {
    int base = (blockIdx.x * blockDim.x + threadIdx.x) * 4;
    if (base >= E) return;
    int cnt = min(4, E - base);
    int s[4], d[4];
    if (g_is64) {
        const long long* p = (const long long*)ei;
        #pragma unroll
        for (int j = 0; j < 4; ++j) if (j < cnt) {
            s[j] = (int)p[base + j]; d[j] = (int)p[E + base + j];
        }
    } else {
        const int* p = (const int*)ei;
        #pragma unroll
        for (int j = 0; j < 4; ++j) if (j < cnt) {
            s[j] = p[base + j]; d[j] = p[E + base + j];
        }
    }
    #pragma unroll
    for (int j = 0; j < 4; ++j) if (j < cnt) {
        g_src[base + j] = s[j];
        g_dst[base + j] = d[j];
    }
    #pragma unroll
    for (int j = 0; j < 4; ++j) if (j < cnt)
        atomicAdd(&g_deg[d[j]], 1);
}

// ------- scan: single-pass exclusive scan of deg (decoupled lookback)
__global__ __launch_bounds__(256) void k_scan(int n) {
    int b = blockIdx.x;
    int i = b * 256 + threadIdx.x;
    int v = (i < n) ? g_deg[i] : 0;
    int lane = threadIdx.x & 31, w = threadIdx.x >> 5;

    int s = v;
    #pragma unroll
    for (int o = 1; o < 32; o <<= 1) {
        int t = __shfl_up_sync(0xFFFFFFFFu, s, o);
        if (lane >= o) s += t;
    }
    __shared__ int wsum[8];
    __shared__ int s_prev;
    if (lane == 31) wsum[w] = s;
    __syncthreads();
    if (w == 0) {
        int t = (lane < 8) ? wsum[lane] : 0;
        #pragma unroll
        for (int o = 1; o < 8; o <<= 1) {
            int u = __shfl_up_sync(0xFFFFFFFFu, t, o);
            if (lane >= o) t += u;
        }
        if (lane < 8) wsum[lane] = t;
    }
    __syncthreads();
    int incl = s + (w > 0 ? wsum[w - 1] : 0);

    if (threadIdx.x == 255)
        atomicExch(&g_part[b], (1ULL << 32) | (unsigned)incl);

    if (threadIdx.x < 32) {
        int sum = 0;
        for (int p = b - 1 - lane; p >= 0; p -= 32) {
            unsigned long long pk;
            volatile unsigned long long* pp = &g_part[p];
            do { pk = *pp; } while (!(pk >> 32));
            sum += (int)(unsigned)pk;
        }
        #pragma unroll
        for (int o = 16; o > 0; o >>= 1)
            sum += __shfl_xor_sync(0xFFFFFFFFu, sum, o);
        if (threadIdx.x == 0) s_prev = sum;
    }
    __syncthreads();

    if (i < n) {
        int off = s_prev + incl - v;
        g_off[i] = off;
        g_cur[i] = off;
    }
}

// ------- csr: scatter src ids into CSR order (4 edges/thread) --------
__global__ void k_csr(int E) {
    int base = (blockIdx.x * blockDim.x + threadIdx.x) * 4;
    if (base >= E) return;
    int cnt = min(4, E - base);
    int d[4], sv[4], p[4];
    #pragma unroll
    for (int j = 0; j < 4; ++j) if (j < cnt) {
        d[j]  = g_dst[base + j];
        sv[j] = g_src[base + j];
    }
    #pragma unroll
    for (int j = 0; j < 4; ++j) if (j < cnt)
        p[j] = atomicAdd(&g_cur[d[j]], 1);
    #pragma unroll
    for (int j = 0; j < 4; ++j) if (j < cnt)
        g_csr[p[j]] = sv[j];
}

// ---------------- GEMM1: h1 = x @ W1^T + b1 -> [N,64] fp16 -----------
__global__ __launch_bounds__(256) void k_gemm1(
    const float* __restrict__ x, const float* __restrict__ W,
    const float* __restrict__ b, int n)
{
    __shared__ __align__(16) float xs[64][68];
    __shared__ __align__(16) float ws[64][68];
    int tid  = threadIdx.x;
    int row0 = blockIdx.x * 64;
    int tx = tid & 15, ty = tid >> 4;

    float acc[4][4];
    #pragma unroll
    for (int i = 0; i < 4; ++i)
        #pragma unroll
        for (int j = 0; j < 4; ++j) acc[i][j] = 0.f;

    for (int kk = 0; kk < NFEAT; kk += 64) {
        #pragma unroll
        for (int it = 0; it < 4; ++it) {
            int idx = tid + it * 256;
            int r = idx >> 4, k4 = idx & 15;
            float4 v = make_float4(0.f, 0.f, 0.f, 0.f);
            int row = row0 + r;
            if (row < n)
                v = __ldg((const float4*)(x + (size_t)row * NFEAT + kk) + k4);
            xs[k4 * 4 + 0][r] = v.x; xs[k4 * 4 + 1][r] = v.y;
            xs[k4 * 4 + 2][r] = v.z; xs[k4 * 4 + 3][r] = v.w;
        }
        #pragma unroll
        for (int it = 0; it < 4; ++it) {
            int idx = tid + it * 256;
            int c = idx >> 4, k4 = idx & 15;
            float4 v = __ldg((const float4*)(W + (size_t)c * NFEAT + kk) + k4);
            ws[k4 * 4 + 0][c] = v.x; ws[k4 * 4 + 1][c] = v.y;
            ws[k4 * 4 + 2][c] = v.z; ws[k4 * 4 + 3][c] = v.w;
        }
        __syncthreads();
        #pragma unroll
        for (int k = 0; k < 64; ++k) {
            float4 xv = *(const float4*)&xs[k][ty * 4];
            float4 wv = *(const float4*)&ws[k][tx * 4];
            float ax[4] = {xv.x, xv.y, xv.z, xv.w};
            float aw[4] = {wv.x, wv.y, wv.z, wv.w};
            #pragma unroll
            for (int i = 0; i < 4; ++i)
                #pragma unroll
                for (int j = 0; j < 4; ++j) acc[i][j] += ax[i] * aw[j];
        }
        __syncthreads();
    }

    float4 bb = __ldg((const float4*)b + tx);
    #pragma unroll
    for (int i = 0; i < 4; ++i) {
        int row = row0 + ty * 4 + i;
        if (row < n) {
            __half2 p0 = __floats2half2_rn(acc[i][0] + bb.x, acc[i][1] + bb.y);
            __half2 p1 = __floats2half2_rn(acc[i][2] + bb.z, acc[i][3] + bb.w);
            uint2 o;
            o.x = *(unsigned*)&p0; o.y = *(unsigned*)&p1;
            ((uint2*)g_h1h)[row * 16 + tx] = o;   // h1
            ((uint2*)g_a1h)[row * 16 + tx] = o;   // agg1 init = self-loop msg
        }
    }
}

// ---------------- scatter1: agg1[dst] += h1[src]  (8 lanes/edge) -----
__global__ __launch_bounds__(256) void k_scatter1(int E) {
    int t = blockIdx.x * blockDim.x + threadIdx.x;
    int e = t >> 3;
    if (e >= E) return;
    int lane = t & 7;
    int s = __ldg(&g_src[e]);
    int d = __ldg(&g_dst[e]);
    uint4 v = __ldg(&g_h1h[s * 8 + lane]);
    asm volatile("red.global.add.noftz.v4.f16x2 [%0], {%1,%2,%3,%4};"
                 :: "l"(&g_a1h[d * 8 + lane]),
                    "r"(v.x), "r"(v.y), "r"(v.z), "r"(v.w) : "memory");
}

// ---------------- GEMM2: h2 = relu(agg1/(deg+1)) @ W2^T + b2 ---------
__global__ __launch_bounds__(160) void k_gemm2(
    const float* __restrict__ W, const float* __restrict__ b, int n)
{
    __shared__ __align__(16) float rs[64][68];
    __shared__ __align__(16) float ws[64][44];
    int tid  = threadIdx.x;
    int row0 = blockIdx.x * 64;

    for (int idx = tid; idx < 1024; idx += 160) {
        int r = idx >> 4, k4 = idx & 15;
        int row = row0 + r;
        float4 v = make_float4(0.f, 0.f, 0.f, 0.f);
        if (row < n) {
            float iv = 1.0f / (float)(__ldg(&g_deg[row]) + 1);
            uint2 a = ((const uint2*)g_a1h)[row * 16 + k4];
            float2 f0 = __half22float2(*(__half2*)&a.x);
            float2 f1 = __half22float2(*(__half2*)&a.y);
            v.x = fmaxf(f0.x * iv, 0.f); v.y = fmaxf(f0.y * iv, 0.f);
            v.z = fmaxf(f1.x * iv, 0.f); v.w = fmaxf(f1.y * iv, 0.f);
        }
        rs[k4 * 4 + 0][r] = v.x; rs[k4 * 4 + 1][r] = v.y;
        rs[k4 * 4 + 2][r] = v.z; rs[k4 * 4 + 3][r] = v.w;
    }
    for (int idx = tid; idx < 640; idx += 160) {
        int c = idx >> 4, k4 = idx & 15;
        float4 v = __ldg((const float4*)(W + (size_t)c * NHID) + k4);
        ws[k4 * 4 + 0][c] = v.x; ws[k4 * 4 + 1][c] = v.y;
        ws[k4 * 4 + 2][c] = v.z; ws[k4 * 4 + 3][c] = v.w;
    }
    __syncthreads();

    int tx = tid % 10, ty = tid / 10;
    float acc[4][4];
    #pragma unroll
    for (int i = 0; i < 4; ++i)
        #pragma unroll
        for (int j = 0; j < 4; ++j) acc[i][j] = 0.f;

    #pragma unroll
    for (int k = 0; k < 64; ++k) {
        float4 xv = *(const float4*)&rs[k][ty * 4];
        float4 wv = *(const float4*)&ws[k][tx * 4];
        float a0[4] = {xv.x, xv.y, xv.z, xv.w};
        float a1[4] = {wv.x, wv.y, wv.z, wv.w};
        #pragma unroll
        for (int i = 0; i < 4; ++i)
            #pragma unroll
            for (int j = 0; j < 4; ++j) acc[i][j] += a0[i] * a1[j];
    }

    float4 bb = __ldg((const float4*)b + tx);
    #pragma unroll
    for (int i = 0; i < 4; ++i) {
        int row = row0 + ty * 4 + i;
        if (row < n) {
            __half2 p0 = __floats2half2_rn(acc[i][0] + bb.x, acc[i][1] + bb.y);
            __half2 p1 = __floats2half2_rn(acc[i][2] + bb.z, acc[i][3] + bb.w);
            uint2 o;
            o.x = *(unsigned*)&p0; o.y = *(unsigned*)&p1;
            ((uint2*)g_h2h)[row * 10 + tx] = o;
        }
    }
}

// ---- agg2 + log_softmax: out = lsm((h2[row] + sum h2[csr])/(deg+1)) --
__global__ __launch_bounds__(256) void k_agg2(float* __restrict__ out, int n) {
    int row = (blockIdx.x * 256 + threadIdx.x) >> 5;
    if (row >= n) return;
    int lane = threadIdx.x & 31;
    int start = g_off[row], deg = g_deg[row], end = start + deg;
    bool act = (lane < 20);
    int fofs = act ? lane : 0;

    float ax = 0.f, ay = 0.f;
    for (int base = start; base < end; base += 32) {
        int cnt = min(32, end - base);
        int idx = 0;
        if (base + lane < end) idx = __ldg(&g_csr[base + lane]);
        int jj = 0;
        for (; jj + 4 <= cnt; jj += 4) {
            int s0 = __shfl_sync(0xFFFFFFFFu, idx, jj);
            int s1 = __shfl_sync(0xFFFFFFFFu, idx, jj + 1);
            int s2 = __shfl_sync(0xFFFFFFFFu, idx, jj + 2);
            int s3 = __shfl_sync(0xFFFFFFFFu, idx, jj + 3);
            if (act) {
                unsigned v0 = __ldg(&g_h2h[s0 * 20 + fofs]);
                unsigned v1 = __ldg(&g_h2h[s1 * 20 + fofs]);
                unsigned v2 = __ldg(&g_h2h[s2 * 20 + fofs]);
                unsigned v3 = __ldg(&g_h2h[s3 * 20 + fofs]);
                float2 f0 = __half22float2(*(__half2*)&v0);
                float2 f1 = __half22float2(*(__half2*)&v1);
                float2 f2 = __half22float2(*(__half2*)&v2);
                float2 f3 = __half22float2(*(__half2*)&v3);
                ax += (f0.x + f1.x) + (f2.x + f3.x);
                ay += (f0.y + f1.y) + (f2.y + f3.y);
            }
        }
        for (; jj < cnt; ++jj) {
            int s0 = __shfl_sync(0xFFFFFFFFu, idx, jj);
            if (act) {
                unsigned v0 = __ldg(&g_h2h[s0 * 20 + fofs]);
                float2 f0 = __half22float2(*(__half2*)&v0);
                ax += f0.x; ay += f0.y;
            }
        }
    }

    float x0 = -3.4e38f, x1 = -3.4e38f;
    float inv = 1.0f / (float)(deg + 1);
    if (act) {
        unsigned vs = g_h2h[row * 20 + fofs];
        float2 fs = __half22float2(*(__half2*)&vs);
        x0 = (ax + fs.x) * inv;
        x1 = (ay + fs.y) * inv;
    }
    float m = fmaxf(x0, x1);
    #pragma unroll
    for (int o = 16; o > 0; o >>= 1)
        m = fmaxf(m, __shfl_xor_sync(0xFFFFFFFFu, m, o));
    float s = act ? (expf(x0 - m) + expf(x1 - m)) : 0.f;
    #pragma unroll
    for (int o = 16; o > 0; o >>= 1)
        s += __shfl_xor_sync(0xFFFFFFFFu, s, o);
    float l = m + logf(s);
    if (act) {
        float2 o2;
        o2.x = x0 - l; o2.y = x1 - l;
        ((float2*)(out + (size_t)row * NCLS))[lane] = o2;
    }
}

// ---------------- side stream for prep overlap (static init) ---------
static cudaStream_t s_prep  = nullptr;
static cudaEvent_t  s_eFork = nullptr, s_eHist = nullptr, s_eCsr = nullptr;
namespace {
struct SInit {
    SInit() {
        cudaStreamCreateWithFlags(&s_prep, cudaStreamNonBlocking);
        cudaEventCreateWithFlags(&s_eFork, cudaEventDisableTiming);
        cudaEventCreateWithFlags(&s_eHist, cudaEventDisableTiming);
        cudaEventCreateWithFlags(&s_eCsr,  cudaEventDisableTiming);
    }
};
SInit g_sinit;
}

// ---------------- launch ----------------
extern "C" void kernel_launch(void* const* d_in, const int* in_sizes, int n_in,
                              void* d_out, int out_size)
{
    const float* x  = (const float*)d_in[0];
    const void*  ei = d_in[1];
    const float* W1 = (const float*)d_in[2];
    const float* b1 = (const float*)d_in[3];
    const float* W2 = (const float*)d_in[4];
    const float* b2 = (const float*)d_in[5];
    float* out = (float*)d_out;

    int n  = in_sizes[0] / NFEAT;     // 100000
    int E  = in_sizes[1] / 2;         // 1600000
    int nb = (n + 255) / 256;         // 391
    int e4 = (E + 3) / 4;

    bool fork = s_prep && s_eFork && s_eHist && s_eCsr;
    cudaStream_t sp = fork ? s_prep : (cudaStream_t)0;

    if (fork) {
        cudaEventRecord(s_eFork, 0);
        cudaStreamWaitEvent(sp, s_eFork, 0);
    }
    // prep chain (fork stream): pre -> hist -> scan -> csr
    k_pre <<<nb, 256, 0, sp>>>((const unsigned*)ei, n);
    k_hist<<<(e4 + 255) / 256, 256, 0, sp>>>(ei, E);
    if (fork) cudaEventRecord(s_eHist, sp);
    k_scan<<<nb, 256, 0, sp>>>(n);
    k_csr <<<(e4 + 255) / 256, 256, 0, sp>>>(E);
    if (fork) cudaEventRecord(s_eCsr, sp);

    // main chain
    k_gemm1<<<(n + 63) / 64, 256>>>(x, W1, b1, n);
    if (fork) cudaStreamWaitEvent(0, s_eHist, 0);     // need src/dst/deg
    k_scatter1<<<(E * 8 + 255) / 256, 256>>>(E);
    k_gemm2<<<(n + 63) / 64, 160>>>(W2, b2, n);
    if (fork) cudaStreamWaitEvent(0, s_eCsr, 0);      // need csr/off
    k_agg2<<<(n * 32 + 255) / 256, 256>>>(out, n);
}

// round 9
// speedup vs baseline: 1.2974x; 1.2974x over previous
#include <cuda_runtime.h>
#include <cuda_fp16.h>

#define N_MAX   100000
#define E_MAX   1600000
#define NFEAT   128
#define NHID    64
#define NCLS    40

// ---------------- device scratch (allocation-free) ----------------
__device__ int g_is64;
__device__ int g_deg[N_MAX];
__device__ __align__(16) uint4 g_h1h[N_MAX * 8];   // h1  [N,64] fp16
__device__ __align__(16) uint4 g_a1h[N_MAX * 8];   // agg1[N,64] fp16 (REDG)
__device__ __align__(16) uint4 g_h2h[N_MAX * 5];   // h2  [N,40] fp16
__device__ __align__(16) uint4 g_a2h[N_MAX * 5];   // agg2[N,40] fp16 (REDG)

static __device__ __forceinline__ unsigned smem_u32(const void* p) {
    return (unsigned)__cvta_generic_to_shared(p);
}

// ====== GEMM1 (tensor core): h1 = x @ W1^T + b1 -> [N,64] fp16 =======
// Tile M=128 (8 warps x m16), N=64, K in 2 chunks of 64. Also zeroes deg
// and detects edge dtype (prologue), since it is the first kernel.
__global__ __launch_bounds__(256) void k_gemm1(
    const float* __restrict__ x, const float* __restrict__ W,
    const float* __restrict__ b, const unsigned* __restrict__ ei, int n)
{
    // -- housekeeping prologue --
    int gid = blockIdx.x * 256 + threadIdx.x;
    if (gid < n) g_deg[gid] = 0;
    if (gid == 0) {
        unsigned hi = 0;
        #pragma unroll
        for (int j = 1; j < 64; j += 2) hi |= ei[j];
        g_is64 = (hi == 0u) ? 1 : 0;
    }

    __shared__ __align__(16) __half xs[128][72];  // 144B stride: 16B-multiple
    __shared__ __align__(16) __half ws[64][72];
    int tid  = threadIdx.x;
    int warp = tid >> 5, lane = tid & 31;
    int row0 = blockIdx.x * 128;
    int m0   = warp * 16;

    float acc[8][4];
    #pragma unroll
    for (int j = 0; j < 8; ++j)
        #pragma unroll
        for (int i = 0; i < 4; ++i) acc[j][i] = 0.f;

    for (int kc = 0; kc < 2; ++kc) {
        int k0g = kc * 64;
        // x chunk: 128 rows x 16 float4 -> fp16 smem
        #pragma unroll
        for (int i = 0; i < 8; ++i) {
            int idx = tid + i * 256;          // 0..2047
            int r = idx >> 4, c4 = idx & 15;
            float4 v = make_float4(0.f, 0.f, 0.f, 0.f);
            if (row0 + r < n)
                v = __ldg((const float4*)(x + (size_t)(row0 + r) * NFEAT + k0g) + c4);
            *(__half2*)&xs[r][c4 * 4]     = __floats2half2_rn(v.x, v.y);
            *(__half2*)&xs[r][c4 * 4 + 2] = __floats2half2_rn(v.z, v.w);
        }
        // W chunk: 64 rows x 16 float4 -> fp16 smem
        #pragma unroll
        for (int i = 0; i < 4; ++i) {
            int idx = tid + i * 256;          // 0..1023
            int r = idx >> 4, c4 = idx & 15;
            float4 v = __ldg((const float4*)(W + (size_t)r * NFEAT + k0g) + c4);
            *(__half2*)&ws[r][c4 * 4]     = __floats2half2_rn(v.x, v.y);
            *(__half2*)&ws[r][c4 * 4 + 2] = __floats2half2_rn(v.z, v.w);
        }
        __syncthreads();

        #pragma unroll
        for (int kk = 0; kk < 4; ++kk) {
            int k0 = kk * 16;
            // A fragment: ldmatrix x4 (m16 x k16), row-major
            unsigned a0, a1, a2, a3;
            {
                int r = m0 + (lane & 7) + ((lane >> 3) & 1) * 8;
                int c = k0 + (lane >> 4) * 8;
                unsigned addr = smem_u32(&xs[r][c]);
                asm volatile(
                    "ldmatrix.sync.aligned.m8n8.x4.shared.b16 {%0,%1,%2,%3}, [%4];"
                    : "=r"(a0), "=r"(a1), "=r"(a2), "=r"(a3) : "r"(addr));
            }
            #pragma unroll
            for (int j2 = 0; j2 < 4; ++j2) {   // two n8 tiles per ldmatrix
                int n0 = j2 * 16;
                // B fragment: ws is [n][k] -> NON-trans ldmatrix gives
                // thread t: ws[n0+t/4][k0+2(t%4)+{0,1}] = B[k][n] as required.
                unsigned b0, b1, b2, b3;
                {
                    int r = n0 + (lane & 7) + (lane >> 4) * 8;
                    int c = k0 + ((lane >> 3) & 1) * 8;
                    unsigned addr = smem_u32(&ws[r][c]);
                    asm volatile(
                        "ldmatrix.sync.aligned.m8n8.x4.shared.b16 {%0,%1,%2,%3}, [%4];"
                        : "=r"(b0), "=r"(b1), "=r"(b2), "=r"(b3) : "r"(addr));
                }
                float* c0 = acc[j2 * 2];
                asm volatile(
                    "mma.sync.aligned.m16n8k16.row.col.f32.f16.f16.f32 "
                    "{%0,%1,%2,%3}, {%4,%5,%6,%7}, {%8,%9}, {%0,%1,%2,%3};"
                    : "+f"(c0[0]), "+f"(c0[1]), "+f"(c0[2]), "+f"(c0[3])
                    : "r"(a0), "r"(a1), "r"(a2), "r"(a3), "r"(b0), "r"(b1));
                float* c1 = acc[j2 * 2 + 1];
                asm volatile(
                    "mma.sync.aligned.m16n8k16.row.col.f32.f16.f16.f32 "
                    "{%0,%1,%2,%3}, {%4,%5,%6,%7}, {%8,%9}, {%0,%1,%2,%3};"
                    : "+f"(c1[0]), "+f"(c1[1]), "+f"(c1[2]), "+f"(c1[3])
                    : "r"(a0), "r"(a1), "r"(a2), "r"(a3), "r"(b2), "r"(b3));
            }
        }
        __syncthreads();
    }

    // epilogue: +bias, fp16, write h1 and a1 (self-loop init)
    int rA = row0 + m0 + (lane >> 2);
    int rB = rA + 8;
    #pragma unroll
    for (int j = 0; j < 8; ++j) {
        int nn = j * 8 + (lane & 3) * 2;
        float bx = __ldg(&b[nn]), by = __ldg(&b[nn + 1]);
        if (rA < n) {
            __half2 h = __floats2half2_rn(acc[j][0] + bx, acc[j][1] + by);
            unsigned wv = *(unsigned*)&h;
            ((unsigned*)g_h1h)[rA * 32 + nn / 2] = wv;
            ((unsigned*)g_a1h)[rA * 32 + nn / 2] = wv;
        }
        if (rB < n) {
            __half2 h = __floats2half2_rn(acc[j][2] + bx, acc[j][3] + by);
            unsigned wv = *(unsigned*)&h;
            ((unsigned*)g_h1h)[rB * 32 + nn / 2] = wv;
            ((unsigned*)g_a1h)[rB * 32 + nn / 2] = wv;
        }
    }
}

// ====== scatter1: agg1[dst] += h1[src], fused edge decode + degree ====
__global__ __launch_bounds__(256) void k_scatter1(const void* __restrict__ ei, int E) {
    int t = blockIdx.x * blockDim.x + threadIdx.x;
    int e = t >> 3;
    if (e >= E) return;
    int lane = t & 7;
    int s, d;
    if (g_is64) {
        const long long* p = (const long long*)ei;
        s = (int)__ldg(&p[e]); d = (int)__ldg(&p[E + e]);
    } else {
        const int* p = (const int*)ei;
        s = __ldg(&p[e]); d = __ldg(&p[E + e]);
    }
    if (lane == 0) atomicAdd(&g_deg[d], 1);
    uint4 v = __ldg(&g_h1h[s * 8 + lane]);
    asm volatile("red.global.add.noftz.v4.f16x2 [%0], {%1,%2,%3,%4};"
                 :: "l"(&g_a1h[d * 8 + lane]),
                    "r"(v.x), "r"(v.y), "r"(v.z), "r"(v.w) : "memory");
}

// ====== GEMM2: h2 = relu(agg1/(deg+1)) @ W2^T + b2 -> [N,40] fp16 ====
__global__ __launch_bounds__(160) void k_gemm2(
    const float* __restrict__ W, const float* __restrict__ b, int n)
{
    __shared__ __align__(16) float rs[64][68];
    __shared__ __align__(16) float ws[64][44];
    int tid  = threadIdx.x;
    int row0 = blockIdx.x * 64;

    for (int idx = tid; idx < 1024; idx += 160) {
        int r = idx >> 4, k4 = idx & 15;
        int row = row0 + r;
        float4 v = make_float4(0.f, 0.f, 0.f, 0.f);
        if (row < n) {
            float iv = 1.0f / (float)(__ldg(&g_deg[row]) + 1);
            uint2 a = ((const uint2*)g_a1h)[row * 16 + k4];
            float2 f0 = __half22float2(*(__half2*)&a.x);
            float2 f1 = __half22float2(*(__half2*)&a.y);
            v.x = fmaxf(f0.x * iv, 0.f); v.y = fmaxf(f0.y * iv, 0.f);
            v.z = fmaxf(f1.x * iv, 0.f); v.w = fmaxf(f1.y * iv, 0.f);
        }
        rs[k4 * 4 + 0][r] = v.x; rs[k4 * 4 + 1][r] = v.y;
        rs[k4 * 4 + 2][r] = v.z; rs[k4 * 4 + 3][r] = v.w;
    }
    for (int idx = tid; idx < 640; idx += 160) {
        int c = idx >> 4, k4 = idx & 15;
        float4 v = __ldg((const float4*)(W + (size_t)c * NHID) + k4);
        ws[k4 * 4 + 0][c] = v.x; ws[k4 * 4 + 1][c] = v.y;
        ws[k4 * 4 + 2][c] = v.z; ws[k4 * 4 + 3][c] = v.w;
    }
    __syncthreads();

    int tx = tid % 10, ty = tid / 10;
    float acc[4][4];
    #pragma unroll
    for (int i = 0; i < 4; ++i)
        #pragma unroll
        for (int j = 0; j < 4; ++j) acc[i][j] = 0.f;

    #pragma unroll
    for (int k = 0; k < 64; ++k) {
        float4 xv = *(const float4*)&rs[k][ty * 4];
        float4 wv = *(const float4*)&ws[k][tx * 4];
        float a0[4] = {xv.x, xv.y, xv.z, xv.w};
        float a1[4] = {wv.x, wv.y, wv.z, wv.w};
        #pragma unroll
        for (int i = 0; i < 4; ++i)
            #pragma unroll
            for (int j = 0; j < 4; ++j) acc[i][j] += a0[i] * a1[j];
    }

    float4 bb = __ldg((const float4*)b + tx);
    #pragma unroll
    for (int i = 0; i < 4; ++i) {
        int row = row0 + ty * 4 + i;
        if (row < n) {
            __half2 p0 = __floats2half2_rn(acc[i][0] + bb.x, acc[i][1] + bb.y);
            __half2 p1 = __floats2half2_rn(acc[i][2] + bb.z, acc[i][3] + bb.w);
            uint2 o;
            o.x = *(unsigned*)&p0; o.y = *(unsigned*)&p1;
            ((uint2*)g_h2h)[row * 10 + tx] = o;
            ((uint2*)g_a2h)[row * 10 + tx] = o;
        }
    }
}

// ====== scatter2: agg2[dst] += h2[src], fused edge decode =============
__global__ __launch_bounds__(320) void k_scatter2(const void* __restrict__ ei, int E) {
    int t = blockIdx.x * blockDim.x + threadIdx.x;
    int e = t / 5;
    if (e >= E) return;
    int lane = t - e * 5;
    int s, d;
    if (g_is64) {
        const long long* p = (const long long*)ei;
        s = (int)__ldg(&p[e]); d = (int)__ldg(&p[E + e]);
    } else {
        const int* p = (const int*)ei;
        s = __ldg(&p[e]); d = __ldg(&p[E + e]);
    }
    uint4 v = __ldg(&g_h2h[s * 5 + lane]);
    asm volatile("red.global.add.noftz.v4.f16x2 [%0], {%1,%2,%3,%4};"
                 :: "l"(&g_a2h[d * 5 + lane]),
                    "r"(v.x), "r"(v.y), "r"(v.z), "r"(v.w) : "memory");
}

// ====== finalize: out = log_softmax(agg2/(deg+1))  (warp/row) =========
__global__ __launch_bounds__(256) void k_finalize(float* __restrict__ out, int n) {
    int row  = (blockIdx.x * blockDim.x + threadIdx.x) >> 5;
    int lane = threadIdx.x & 31;
    if (row >= n) return;
    float x0 = -3.4e38f, x1 = -3.4e38f;
    float iv = 1.0f / (float)(g_deg[row] + 1);
    if (lane < 20) {
        unsigned w = ((const unsigned*)g_a2h)[row * 20 + lane];
        float2 f = __half22float2(*(__half2*)&w);
        x0 = f.x * iv; x1 = f.y * iv;
    }
    float m = fmaxf(x0, x1);
    #pragma unroll
    for (int o = 16; o > 0; o >>= 1)
        m = fmaxf(m, __shfl_xor_sync(0xFFFFFFFFu, m, o));
    float s = (lane < 20) ? (expf(x0 - m) + expf(x1 - m)) : 0.f;
    #pragma unroll
    for (int o = 16; o > 0; o >>= 1)
        s += __shfl_xor_sync(0xFFFFFFFFu, s, o);
    float l = m + logf(s);
    if (lane < 20) {
        float2 o2;
        o2.x = x0 - l; o2.y = x1 - l;
        ((float2*)(out + (size_t)row * NCLS))[lane] = o2;
    }
}

// ---------------- launch ----------------
extern "C" void kernel_launch(void* const* d_in, const int* in_sizes, int n_in,
                              void* d_out, int out_size)
{
    const float* x  = (const float*)d_in[0];
    const void*  ei = d_in[1];
    const float* W1 = (const float*)d_in[2];
    const float* b1 = (const float*)d_in[3];
    const float* W2 = (const float*)d_in[4];
    const float* b2 = (const float*)d_in[5];
    float* out = (float*)d_out;

    int n = in_sizes[0] / NFEAT;      // 100000
    int E = in_sizes[1] / 2;          // 1600000

    k_gemm1   <<<(n + 127) / 128, 256>>>(x, W1, b1, (const unsigned*)ei, n);
    k_scatter1<<<(E * 8 + 255) / 256, 256>>>(ei, E);
    k_gemm2   <<<(n + 63) / 64, 160>>>(W2, b2, n);
    k_scatter2<<<(E * 5 + 319) / 320, 320>>>(ei, E);
    k_finalize<<<(n + 7) / 8, 256>>>(out, n);
}

// round 12
// speedup vs baseline: 1.5555x; 1.1989x over previous
#include <cuda_runtime.h>
#include <cuda_fp16.h>

#define N_MAX   100000
#define E_MAX   1600000
#define NFEAT   128
#define NHID    64
#define NCLS    40

// ---------------- device scratch (allocation-free) ----------------
__device__ int g_is64;
__device__ int g_deg[N_MAX];
__device__ __align__(16) uint4 g_h1h[N_MAX * 8];   // h1  [N,64] fp16
__device__ __align__(16) uint4 g_a1h[N_MAX * 8];   // agg1[N,64] fp16 (REDG)
__device__ __align__(16) uint4 g_h2h[N_MAX * 5];   // h2  [N,40] fp16
__device__ __align__(16) uint4 g_a2h[N_MAX * 5];   // agg2[N,40] fp16 (REDG)

static __device__ __forceinline__ unsigned smem_u32(const void* p) {
    return (unsigned)__cvta_generic_to_shared(p);
}

// ====== GEMM1 (tensor core): h1 = x @ W1^T + b1 -> [N,64] fp16 =======
__global__ __launch_bounds__(256) void k_gemm1(
    const float* __restrict__ x, const float* __restrict__ W,
    const float* __restrict__ b, const unsigned* __restrict__ ei, int n)
{
    // -- housekeeping prologue --
    int gid = blockIdx.x * 256 + threadIdx.x;
    if (gid < n) g_deg[gid] = 0;
    if (gid == 0) {
        unsigned hi = 0;
        #pragma unroll
        for (int j = 1; j < 64; j += 2) hi |= ei[j];
        g_is64 = (hi == 0u) ? 1 : 0;
    }

    __shared__ __align__(16) __half xs[128][72];
    __shared__ __align__(16) __half ws[64][72];
    int tid  = threadIdx.x;
    int warp = tid >> 5, lane = tid & 31;
    int row0 = blockIdx.x * 128;
    int m0   = warp * 16;

    float acc[8][4];
    #pragma unroll
    for (int j = 0; j < 8; ++j)
        #pragma unroll
        for (int i = 0; i < 4; ++i) acc[j][i] = 0.f;

    for (int kc = 0; kc < 2; ++kc) {
        int k0g = kc * 64;
        #pragma unroll
        for (int i = 0; i < 8; ++i) {
            int idx = tid + i * 256;
            int r = idx >> 4, c4 = idx & 15;
            float4 v = make_float4(0.f, 0.f, 0.f, 0.f);
            if (row0 + r < n)
                v = __ldg((const float4*)(x + (size_t)(row0 + r) * NFEAT + k0g) + c4);
            *(__half2*)&xs[r][c4 * 4]     = __floats2half2_rn(v.x, v.y);
            *(__half2*)&xs[r][c4 * 4 + 2] = __floats2half2_rn(v.z, v.w);
        }
        #pragma unroll
        for (int i = 0; i < 4; ++i) {
            int idx = tid + i * 256;
            int r = idx >> 4, c4 = idx & 15;
            float4 v = __ldg((const float4*)(W + (size_t)r * NFEAT + k0g) + c4);
            *(__half2*)&ws[r][c4 * 4]     = __floats2half2_rn(v.x, v.y);
            *(__half2*)&ws[r][c4 * 4 + 2] = __floats2half2_rn(v.z, v.w);
        }
        __syncthreads();

        #pragma unroll
        for (int kk = 0; kk < 4; ++kk) {
            int k0 = kk * 16;
            unsigned a0, a1, a2, a3;
            {
                int r = m0 + (lane & 7) + ((lane >> 3) & 1) * 8;
                int c = k0 + (lane >> 4) * 8;
                unsigned addr = smem_u32(&xs[r][c]);
                asm volatile(
                    "ldmatrix.sync.aligned.m8n8.x4.shared.b16 {%0,%1,%2,%3}, [%4];"
                    : "=r"(a0), "=r"(a1), "=r"(a2), "=r"(a3) : "r"(addr));
            }
            #pragma unroll
            for (int j2 = 0; j2 < 4; ++j2) {
                int n0 = j2 * 16;
                unsigned b0, b1, b2, b3;
                {
                    int r = n0 + (lane & 7) + (lane >> 4) * 8;
                    int c = k0 + ((lane >> 3) & 1) * 8;
                    unsigned addr = smem_u32(&ws[r][c]);
                    asm volatile(
                        "ldmatrix.sync.aligned.m8n8.x4.shared.b16 {%0,%1,%2,%3}, [%4];"
                        : "=r"(b0), "=r"(b1), "=r"(b2), "=r"(b3) : "r"(addr));
                }
                float* c0 = acc[j2 * 2];
                asm volatile(
                    "mma.sync.aligned.m16n8k16.row.col.f32.f16.f16.f32 "
                    "{%0,%1,%2,%3}, {%4,%5,%6,%7}, {%8,%9}, {%0,%1,%2,%3};"
                    : "+f"(c0[0]), "+f"(c0[1]), "+f"(c0[2]), "+f"(c0[3])
                    : "r"(a0), "r"(a1), "r"(a2), "r"(a3), "r"(b0), "r"(b1));
                float* c1 = acc[j2 * 2 + 1];
                asm volatile(
                    "mma.sync.aligned.m16n8k16.row.col.f32.f16.f16.f32 "
                    "{%0,%1,%2,%3}, {%4,%5,%6,%7}, {%8,%9}, {%0,%1,%2,%3};"
                    : "+f"(c1[0]), "+f"(c1[1]), "+f"(c1[2]), "+f"(c1[3])
                    : "r"(a0), "r"(a1), "r"(a2), "r"(a3), "r"(b2), "r"(b3));
            }
        }
        __syncthreads();
    }

    int rA = row0 + m0 + (lane >> 2);
    int rB = rA + 8;
    #pragma unroll
    for (int j = 0; j < 8; ++j) {
        int nn = j * 8 + (lane & 3) * 2;
        float bx = __ldg(&b[nn]), by = __ldg(&b[nn + 1]);
        if (rA < n) {
            __half2 h = __floats2half2_rn(acc[j][0] + bx, acc[j][1] + by);
            unsigned wv = *(unsigned*)&h;
            ((unsigned*)g_h1h)[rA * 32 + nn / 2] = wv;
            ((unsigned*)g_a1h)[rA * 32 + nn / 2] = wv;
        }
        if (rB < n) {
            __half2 h = __floats2half2_rn(acc[j][2] + bx, acc[j][3] + by);
            unsigned wv = *(unsigned*)&h;
            ((unsigned*)g_h1h)[rB * 32 + nn / 2] = wv;
            ((unsigned*)g_a1h)[rB * 32 + nn / 2] = wv;
        }
    }
}

// ====== scatter1: agg1[dst] += h1[src], ILP-2 (8 edges/warp) =========
__global__ __launch_bounds__(256) void k_scatter1(const void* __restrict__ ei, int E) {
    int t = blockIdx.x * blockDim.x + threadIdx.x;
    int warpid = t >> 5;
    int lane = t & 31;
    int grp = lane >> 3, sub = lane & 7;
    int e0 = warpid * 8 + grp;
    if (e0 >= E) return;
    int e1 = e0 + 4;
    bool ok1 = (e1 < E);
    int s0, d0, s1 = 0, d1 = 0;
    if (g_is64) {
        const long long* p = (const long long*)ei;
        s0 = (int)__ldg(&p[e0]); d0 = (int)__ldg(&p[E + e0]);
        if (ok1) { s1 = (int)__ldg(&p[e1]); d1 = (int)__ldg(&p[E + e1]); }
    } else {
        const int* p = (const int*)ei;
        s0 = __ldg(&p[e0]); d0 = __ldg(&p[E + e0]);
        if (ok1) { s1 = __ldg(&p[e1]); d1 = __ldg(&p[E + e1]); }
    }
    if (sub == 0) {
        atomicAdd(&g_deg[d0], 1);
        if (ok1) atomicAdd(&g_deg[d1], 1);
    }
    uint4 va = __ldg(&g_h1h[s0 * 8 + sub]);
    uint4 vb;
    if (ok1) vb = __ldg(&g_h1h[s1 * 8 + sub]);
    asm volatile("red.global.add.noftz.v4.f16x2 [%0], {%1,%2,%3,%4};"
                 :: "l"(&g_a1h[d0 * 8 + sub]),
                    "r"(va.x), "r"(va.y), "r"(va.z), "r"(va.w) : "memory");
    if (ok1)
        asm volatile("red.global.add.noftz.v4.f16x2 [%0], {%1,%2,%3,%4};"
                     :: "l"(&g_a1h[d1 * 8 + sub]),
                        "r"(vb.x), "r"(vb.y), "r"(vb.z), "r"(vb.w) : "memory");
}

// ====== GEMM2 (tensor core): h2 = relu(agg1/(deg+1)) @ W2^T + b2 =====
// M=128 (8 warps x m16), N=40 (5 n8-tiles via 3 B ldmatrix.x4), K=64.
__global__ __launch_bounds__(256) void k_gemm2(
    const float* __restrict__ W, const float* __restrict__ b, int n)
{
    __shared__ __align__(16) __half rs[128][72];
    __shared__ __align__(16) __half ws[48][72];   // rows 40..47 unused pad
    int tid  = threadIdx.x;
    int warp = tid >> 5, lane = tid & 31;
    int row0 = blockIdx.x * 128;
    int m0   = warp * 16;

    // fill rs = relu(agg1 * 1/(deg+1)) in fp16
    #pragma unroll
    for (int i = 0; i < 4; ++i) {
        int idx = tid + i * 256;          // 0..1023
        int r = idx >> 3, c8 = idx & 7;   // 8 uint4 per row
        int row = row0 + r;
        uint4 a = make_uint4(0, 0, 0, 0);
        float iv = 0.f;
        if (row < n) {
            iv = 1.0f / (float)(__ldg(&g_deg[row]) + 1);
            a = g_a1h[row * 8 + c8];
        }
        float2 f;
        f = __half22float2(*(__half2*)&a.x);
        *(__half2*)&rs[r][c8 * 8 + 0] = __floats2half2_rn(fmaxf(f.x * iv, 0.f), fmaxf(f.y * iv, 0.f));
        f = __half22float2(*(__half2*)&a.y);
        *(__half2*)&rs[r][c8 * 8 + 2] = __floats2half2_rn(fmaxf(f.x * iv, 0.f), fmaxf(f.y * iv, 0.f));
        f = __half22float2(*(__half2*)&a.z);
        *(__half2*)&rs[r][c8 * 8 + 4] = __floats2half2_rn(fmaxf(f.x * iv, 0.f), fmaxf(f.y * iv, 0.f));
        f = __half22float2(*(__half2*)&a.w);
        *(__half2*)&rs[r][c8 * 8 + 6] = __floats2half2_rn(fmaxf(f.x * iv, 0.f), fmaxf(f.y * iv, 0.f));
    }
    // W2 -> ws fp16 (40 rows x 64)
    for (int idx = tid; idx < 640; idx += 256) {
        int r = idx >> 4, c4 = idx & 15;
        float4 v = __ldg((const float4*)(W + (size_t)r * NHID) + c4);
        *(__half2*)&ws[r][c4 * 4]     = __floats2half2_rn(v.x, v.y);
        *(__half2*)&ws[r][c4 * 4 + 2] = __floats2half2_rn(v.z, v.w);
    }
    __syncthreads();

    float acc[5][4];
    #pragma unroll
    for (int j = 0; j < 5; ++j)
        #pragma unroll
        for (int i = 0; i < 4; ++i) acc[j][i] = 0.f;

    #pragma unroll
    for (int kk = 0; kk < 4; ++kk) {
        int k0 = kk * 16;
        unsigned a0, a1, a2, a3;
        {
            int r = m0 + (lane & 7) + ((lane >> 3) & 1) * 8;
            int c = k0 + (lane >> 4) * 8;
            unsigned addr = smem_u32(&rs[r][c]);
            asm volatile(
                "ldmatrix.sync.aligned.m8n8.x4.shared.b16 {%0,%1,%2,%3}, [%4];"
                : "=r"(a0), "=r"(a1), "=r"(a2), "=r"(a3) : "r"(addr));
        }
        #pragma unroll
        for (int l = 0; l < 3; ++l) {     // n0 = 0, 16, 32
            int n0 = l * 16;
            unsigned b0, b1, b2, b3;
            {
                int r = n0 + (lane & 7) + (lane >> 4) * 8;
                int c = k0 + ((lane >> 3) & 1) * 8;
                unsigned addr = smem_u32(&ws[r][c]);
                asm volatile(
                    "ldmatrix.sync.aligned.m8n8.x4.shared.b16 {%0,%1,%2,%3}, [%4];"
                    : "=r"(b0), "=r"(b1), "=r"(b2), "=r"(b3) : "r"(addr));
            }
            float* c0 = acc[l * 2];
            asm volatile(
                "mma.sync.aligned.m16n8k16.row.col.f32.f16.f16.f32 "
                "{%0,%1,%2,%3}, {%4,%5,%6,%7}, {%8,%9}, {%0,%1,%2,%3};"
                : "+f"(c0[0]), "+f"(c0[1]), "+f"(c0[2]), "+f"(c0[3])
                : "r"(a0), "r"(a1), "r"(a2), "r"(a3), "r"(b0), "r"(b1));
            if (l < 2) {                  // 6th n8 tile (n40-47) not needed
                float* c1 = acc[l * 2 + 1];
                asm volatile(
                    "mma.sync.aligned.m16n8k16.row.col.f32.f16.f16.f32 "
                    "{%0,%1,%2,%3}, {%4,%5,%6,%7}, {%8,%9}, {%0,%1,%2,%3};"
                    : "+f"(c1[0]), "+f"(c1[1]), "+f"(c1[2]), "+f"(c1[3])
                    : "r"(a0), "r"(a1), "r"(a2), "r"(a3), "r"(b2), "r"(b3));
            }
        }
    }

    int rA = row0 + m0 + (lane >> 2);
    int rB = rA + 8;
    #pragma unroll
    for (int j = 0; j < 5; ++j) {
        int nn = j * 8 + (lane & 3) * 2;  // 0..39
        float bx = __ldg(&b[nn]), by = __ldg(&b[nn + 1]);
        int wofs = j * 4 + (lane & 3);    // word index 0..19
        if (rA < n) {
            __half2 h = __floats2half2_rn(acc[j][0] + bx, acc[j][1] + by);
            unsigned wv = *(unsigned*)&h;
            ((unsigned*)g_h2h)[rA * 20 + wofs] = wv;
            ((unsigned*)g_a2h)[rA * 20 + wofs] = wv;
        }
        if (rB < n) {
            __half2 h = __floats2half2_rn(acc[j][2] + bx, acc[j][3] + by);
            unsigned wv = *(unsigned*)&h;
            ((unsigned*)g_h2h)[rB * 20 + wofs] = wv;
            ((unsigned*)g_a2h)[rB * 20 + wofs] = wv;
        }
    }
}

// ====== scatter2: agg2[dst] += h2[src], ILP-2, warp-aligned ==========
// 12 edges/warp: lanes 0-29 in 6 groups of 5; each group does edges e0,e0+6.
__global__ __launch_bounds__(256) void k_scatter2(const void* __restrict__ ei, int E) {
    int t = blockIdx.x * blockDim.x + threadIdx.x;
    int warpid = t >> 5;
    int lane = t & 31;
    if (lane >= 30) return;
    int grp = lane / 5, sub = lane - grp * 5;
    int e0 = warpid * 12 + grp;
    if (e0 >= E) return;
    int e1 = e0 + 6;
    bool ok1 = (e1 < E);
    int s0, d0, s1 = 0, d1 = 0;
    if (g_is64) {
        const long long* p = (const long long*)ei;
        s0 = (int)__ldg(&p[e0]); d0 = (int)__ldg(&p[E + e0]);
        if (ok1) { s1 = (int)__ldg(&p[e1]); d1 = (int)__ldg(&p[E + e1]); }
    } else {
        const int* p = (const int*)ei;
        s0 = __ldg(&p[e0]); d0 = __ldg(&p[E + e0]);
        if (ok1) { s1 = __ldg(&p[e1]); d1 = __ldg(&p[E + e1]); }
    }
    uint4 va = __ldg(&g_h2h[s0 * 5 + sub]);
    uint4 vb;
    if (ok1) vb = __ldg(&g_h2h[s1 * 5 + sub]);
    asm volatile("red.global.add.noftz.v4.f16x2 [%0], {%1,%2,%3,%4};"
                 :: "l"(&g_a2h[d0 * 5 + sub]),
                    "r"(va.x), "r"(va.y), "r"(va.z), "r"(va.w) : "memory");
    if (ok1)
        asm volatile("red.global.add.noftz.v4.f16x2 [%0], {%1,%2,%3,%4};"
                     :: "l"(&g_a2h[d1 * 5 + sub]),
                        "r"(vb.x), "r"(vb.y), "r"(vb.z), "r"(vb.w) : "memory");
}

// ====== finalize: out = log_softmax(agg2/(deg+1))  (warp/row) =========
__global__ __launch_bounds__(256) void k_finalize(float* __restrict__ out, int n) {
    int row  = (blockIdx.x * blockDim.x + threadIdx.x) >> 5;
    int lane = threadIdx.x & 31;
    if (row >= n) return;
    float x0 = -3.4e38f, x1 = -3.4e38f;
    float iv = 1.0f / (float)(g_deg[row] + 1);
    if (lane < 20) {
        unsigned w = ((const unsigned*)g_a2h)[row * 20 + lane];
        float2 f = __half22float2(*(__half2*)&w);
        x0 = f.x * iv; x1 = f.y * iv;
    }
    float m = fmaxf(x0, x1);
    #pragma unroll
    for (int o = 16; o > 0; o >>= 1)
        m = fmaxf(m, __shfl_xor_sync(0xFFFFFFFFu, m, o));
    float s = (lane < 20) ? (expf(x0 - m) + expf(x1 - m)) : 0.f;
    #pragma unroll
    for (int o = 16; o > 0; o >>= 1)
        s += __shfl_xor_sync(0xFFFFFFFFu, s, o);
    float l = m + logf(s);
    if (lane < 20) {
        float2 o2;
        o2.x = x0 - l; o2.y = x1 - l;
        ((float2*)(out + (size_t)row * NCLS))[lane] = o2;
    }
}

// ---------------- launch ----------------
extern "C" void kernel_launch(void* const* d_in, const int* in_sizes, int n_in,
                              void* d_out, int out_size)
{
    const float* x  = (const float*)d_in[0];
    const void*  ei = d_in[1];
    const float* W1 = (const float*)d_in[2];
    const float* b1 = (const float*)d_in[3];
    const float* W2 = (const float*)d_in[4];
    const float* b2 = (const float*)d_in[5];
    float* out = (float*)d_out;

    int n = in_sizes[0] / NFEAT;      // 100000
    int E = in_sizes[1] / 2;          // 1600000

    int w1 = (E + 7) / 8;             // scatter1 warps (8 edges/warp)
    int w2 = (E + 11) / 12;           // scatter2 warps (12 edges/warp)

    k_gemm1   <<<(n + 127) / 128, 256>>>(x, W1, b1, (const unsigned*)ei, n);
    k_scatter1<<<(w1 * 32 + 255) / 256, 256>>>(ei, E);
    k_gemm2   <<<(n + 127) / 128, 256>>>(W2, b2, n);
    k_scatter2<<<(w2 * 32 + 255) / 256, 256>>>(ei, E);
    k_finalize<<<(n + 7) / 8, 256>>>(out, n);
}

// round 13
// speedup vs baseline: 1.6023x; 1.0301x over previous
#include <cuda_runtime.h>
#include <cuda_fp16.h>

#define N_MAX   100000
#define E_MAX   1600000
#define NFEAT   128
#define NHID    64
#define NCLS    40

// ---------------- device scratch (allocation-free) ----------------
__device__ int g_is64;
__device__ int g_deg[N_MAX];
__device__ __align__(16) uint4 g_h1h[N_MAX * 8];   // h1  [N,64] fp16
__device__ __align__(16) uint4 g_a1h[N_MAX * 8];   // agg1[N,64] fp16 (REDG)
__device__ __align__(16) uint4 g_h2h[N_MAX * 5];   // h2  [N,40] fp16
__device__ __align__(16) uint4 g_a2h[N_MAX * 5];   // agg2[N,40] fp16 (REDG)

static __device__ __forceinline__ unsigned smem_u32(const void* p) {
    return (unsigned)__cvta_generic_to_shared(p);
}

// ====== GEMM1 (tensor core): h1 = x @ W1^T + b1 -> [N,64] fp16 =======
__global__ __launch_bounds__(256) void k_gemm1(
    const float* __restrict__ x, const float* __restrict__ W,
    const float* __restrict__ b, const unsigned* __restrict__ ei, int n)
{
    // -- housekeeping prologue --
    int gid = blockIdx.x * 256 + threadIdx.x;
    if (gid < n) g_deg[gid] = 0;
    if (gid == 0) {
        unsigned hi = 0;
        #pragma unroll
        for (int j = 1; j < 64; j += 2) hi |= ei[j];
        g_is64 = (hi == 0u) ? 1 : 0;
    }

    __shared__ __align__(16) __half xs[128][72];
    __shared__ __align__(16) __half ws[64][72];
    int tid  = threadIdx.x;
    int warp = tid >> 5, lane = tid & 31;
    int row0 = blockIdx.x * 128;
    int m0   = warp * 16;

    float acc[8][4];
    #pragma unroll
    for (int j = 0; j < 8; ++j)
        #pragma unroll
        for (int i = 0; i < 4; ++i) acc[j][i] = 0.f;

    for (int kc = 0; kc < 2; ++kc) {
        int k0g = kc * 64;
        #pragma unroll
        for (int i = 0; i < 8; ++i) {
            int idx = tid + i * 256;
            int r = idx >> 4, c4 = idx & 15;
            float4 v = make_float4(0.f, 0.f, 0.f, 0.f);
            if (row0 + r < n)
                v = __ldg((const float4*)(x + (size_t)(row0 + r) * NFEAT + k0g) + c4);
            *(__half2*)&xs[r][c4 * 4]     = __floats2half2_rn(v.x, v.y);
            *(__half2*)&xs[r][c4 * 4 + 2] = __floats2half2_rn(v.z, v.w);
        }
        #pragma unroll
        for (int i = 0; i < 4; ++i) {
            int idx = tid + i * 256;
            int r = idx >> 4, c4 = idx & 15;
            float4 v = __ldg((const float4*)(W + (size_t)r * NFEAT + k0g) + c4);
            *(__half2*)&ws[r][c4 * 4]     = __floats2half2_rn(v.x, v.y);
            *(__half2*)&ws[r][c4 * 4 + 2] = __floats2half2_rn(v.z, v.w);
        }
        __syncthreads();

        #pragma unroll
        for (int kk = 0; kk < 4; ++kk) {
            int k0 = kk * 16;
            unsigned a0, a1, a2, a3;
            {
                int r = m0 + (lane & 7) + ((lane >> 3) & 1) * 8;
                int c = k0 + (lane >> 4) * 8;
                unsigned addr = smem_u32(&xs[r][c]);
                asm volatile(
                    "ldmatrix.sync.aligned.m8n8.x4.shared.b16 {%0,%1,%2,%3}, [%4];"
                    : "=r"(a0), "=r"(a1), "=r"(a2), "=r"(a3) : "r"(addr));
            }
            #pragma unroll
            for (int j2 = 0; j2 < 4; ++j2) {
                int n0 = j2 * 16;
                unsigned b0, b1, b2, b3;
                {
                    int r = n0 + (lane & 7) + (lane >> 4) * 8;
                    int c = k0 + ((lane >> 3) & 1) * 8;
                    unsigned addr = smem_u32(&ws[r][c]);
                    asm volatile(
                        "ldmatrix.sync.aligned.m8n8.x4.shared.b16 {%0,%1,%2,%3}, [%4];"
                        : "=r"(b0), "=r"(b1), "=r"(b2), "=r"(b3) : "r"(addr));
                }
                float* c0 = acc[j2 * 2];
                asm volatile(
                    "mma.sync.aligned.m16n8k16.row.col.f32.f16.f16.f32 "
                    "{%0,%1,%2,%3}, {%4,%5,%6,%7}, {%8,%9}, {%0,%1,%2,%3};"
                    : "+f"(c0[0]), "+f"(c0[1]), "+f"(c0[2]), "+f"(c0[3])
                    : "r"(a0), "r"(a1), "r"(a2), "r"(a3), "r"(b0), "r"(b1));
                float* c1 = acc[j2 * 2 + 1];
                asm volatile(
                    "mma.sync.aligned.m16n8k16.row.col.f32.f16.f16.f32 "
                    "{%0,%1,%2,%3}, {%4,%5,%6,%7}, {%8,%9}, {%0,%1,%2,%3};"
                    : "+f"(c1[0]), "+f"(c1[1]), "+f"(c1[2]), "+f"(c1[3])
                    : "r"(a0), "r"(a1), "r"(a2), "r"(a3), "r"(b2), "r"(b3));
            }
        }
        __syncthreads();
    }

    int rA = row0 + m0 + (lane >> 2);
    int rB = rA + 8;
    #pragma unroll
    for (int j = 0; j < 8; ++j) {
        int nn = j * 8 + (lane & 3) * 2;
        float bx = __ldg(&b[nn]), by = __ldg(&b[nn + 1]);
        if (rA < n) {
            __half2 h = __floats2half2_rn(acc[j][0] + bx, acc[j][1] + by);
            unsigned wv = *(unsigned*)&h;
            ((unsigned*)g_h1h)[rA * 32 + nn / 2] = wv;
            ((unsigned*)g_a1h)[rA * 32 + nn / 2] = wv;
        }
        if (rB < n) {
            __half2 h = __floats2half2_rn(acc[j][2] + bx, acc[j][3] + by);
            unsigned wv = *(unsigned*)&h;
            ((unsigned*)g_h1h)[rB * 32 + nn / 2] = wv;
            ((unsigned*)g_a1h)[rB * 32 + nn / 2] = wv;
        }
    }
}

// ====== scatter1: agg1[dst] += h1[src], ILP-4 (16 edges/warp) ========
// 4 groups of 8 lanes; each group handles edges e0, e0+4, e0+8, e0+12.
__global__ __launch_bounds__(256) void k_scatter1(const void* __restrict__ ei, int E) {
    int t = blockIdx.x * blockDim.x + threadIdx.x;
    int warpid = t >> 5;
    int lane = t & 31;
    int grp = lane >> 3, sub = lane & 7;
    int eb = warpid * 16 + grp;
    if (eb >= E) return;

    int s[4], d[4];
    bool ok[4];
    #pragma unroll
    for (int j = 0; j < 4; ++j) {
        int e = eb + j * 4;
        ok[j] = (e < E);
    }
    if (g_is64) {
        const long long* p = (const long long*)ei;
        #pragma unroll
        for (int j = 0; j < 4; ++j) if (ok[j]) {
            int e = eb + j * 4;
            s[j] = (int)__ldg(&p[e]); d[j] = (int)__ldg(&p[E + e]);
        }
    } else {
        const int* p = (const int*)ei;
        #pragma unroll
        for (int j = 0; j < 4; ++j) if (ok[j]) {
            int e = eb + j * 4;
            s[j] = __ldg(&p[e]); d[j] = __ldg(&p[E + e]);
        }
    }
    if (sub == 0) {
        #pragma unroll
        for (int j = 0; j < 4; ++j) if (ok[j]) atomicAdd(&g_deg[d[j]], 1);
    }
    uint4 v[4];
    #pragma unroll
    for (int j = 0; j < 4; ++j) if (ok[j])
        v[j] = __ldg(&g_h1h[s[j] * 8 + sub]);
    #pragma unroll
    for (int j = 0; j < 4; ++j) if (ok[j])
        asm volatile("red.global.add.noftz.v4.f16x2 [%0], {%1,%2,%3,%4};"
                     :: "l"(&g_a1h[d[j] * 8 + sub]),
                        "r"(v[j].x), "r"(v[j].y), "r"(v[j].z), "r"(v[j].w) : "memory");
}

// ====== GEMM2 (tensor core): h2 = relu(agg1/(deg+1)) @ W2^T + b2 =====
// M=128 (8 warps x m16), N=40 (5 n8-tiles via 3 B ldmatrix.x4), K=64.
__global__ __launch_bounds__(256) void k_gemm2(
    const float* __restrict__ W, const float* __restrict__ b, int n)
{
    __shared__ __align__(16) __half rs[128][72];
    __shared__ __align__(16) __half ws[48][72];   // rows 40..47 unused pad
    int tid  = threadIdx.x;
    int warp = tid >> 5, lane = tid & 31;
    int row0 = blockIdx.x * 128;
    int m0   = warp * 16;

    // fill rs = relu(agg1 * 1/(deg+1)) in fp16
    #pragma unroll
    for (int i = 0; i < 4; ++i) {
        int idx = tid + i * 256;          // 0..1023
        int r = idx >> 3, c8 = idx & 7;   // 8 uint4 per row
        int row = row0 + r;
        uint4 a = make_uint4(0, 0, 0, 0);
        float iv = 0.f;
        if (row < n) {
            iv = 1.0f / (float)(__ldg(&g_deg[row]) + 1);
            a = g_a1h[row * 8 + c8];
        }
        float2 f;
        f = __half22float2(*(__half2*)&a.x);
        *(__half2*)&rs[r][c8 * 8 + 0] = __floats2half2_rn(fmaxf(f.x * iv, 0.f), fmaxf(f.y * iv, 0.f));
        f = __half22float2(*(__half2*)&a.y);
        *(__half2*)&rs[r][c8 * 8 + 2] = __floats2half2_rn(fmaxf(f.x * iv, 0.f), fmaxf(f.y * iv, 0.f));
        f = __half22float2(*(__half2*)&a.z);
        *(__half2*)&rs[r][c8 * 8 + 4] = __floats2half2_rn(fmaxf(f.x * iv, 0.f), fmaxf(f.y * iv, 0.f));
        f = __half22float2(*(__half2*)&a.w);
        *(__half2*)&rs[r][c8 * 8 + 6] = __floats2half2_rn(fmaxf(f.x * iv, 0.f), fmaxf(f.y * iv, 0.f));
    }
    // W2 -> ws fp16 (40 rows x 64)
    for (int idx = tid; idx < 640; idx += 256) {
        int r = idx >> 4, c4 = idx & 15;
        float4 v = __ldg((const float4*)(W + (size_t)r * NHID) + c4);
        *(__half2*)&ws[r][c4 * 4]     = __floats2half2_rn(v.x, v.y);
        *(__half2*)&ws[r][c4 * 4 + 2] = __floats2half2_rn(v.z, v.w);
    }
    __syncthreads();

    float acc[5][4];
    #pragma unroll
    for (int j = 0; j < 5; ++j)
        #pragma unroll
        for (int i = 0; i < 4; ++i) acc[j][i] = 0.f;

    #pragma unroll
    for (int kk = 0; kk < 4; ++kk) {
        int k0 = kk * 16;
        unsigned a0, a1, a2, a3;
        {
            int r = m0 + (lane & 7) + ((lane >> 3) & 1) * 8;
            int c = k0 + (lane >> 4) * 8;
            unsigned addr = smem_u32(&rs[r][c]);
            asm volatile(
                "ldmatrix.sync.aligned.m8n8.x4.shared.b16 {%0,%1,%2,%3}, [%4];"
                : "=r"(a0), "=r"(a1), "=r"(a2), "=r"(a3) : "r"(addr));
        }
        #pragma unroll
        for (int l = 0; l < 3; ++l) {     // n0 = 0, 16, 32
            int n0 = l * 16;
            unsigned b0, b1, b2, b3;
            {
                int r = n0 + (lane & 7) + (lane >> 4) * 8;
                int c = k0 + ((lane >> 3) & 1) * 8;
                unsigned addr = smem_u32(&ws[r][c]);
                asm volatile(
                    "ldmatrix.sync.aligned.m8n8.x4.shared.b16 {%0,%1,%2,%3}, [%4];"
                    : "=r"(b0), "=r"(b1), "=r"(b2), "=r"(b3) : "r"(addr));
            }
            float* c0 = acc[l * 2];
            asm volatile(
                "mma.sync.aligned.m16n8k16.row.col.f32.f16.f16.f32 "
                "{%0,%1,%2,%3}, {%4,%5,%6,%7}, {%8,%9}, {%0,%1,%2,%3};"
                : "+f"(c0[0]), "+f"(c0[1]), "+f"(c0[2]), "+f"(c0[3])
                : "r"(a0), "r"(a1), "r"(a2), "r"(a3), "r"(b0), "r"(b1));
            if (l < 2) {                  // 6th n8 tile (n40-47) not needed
                float* c1 = acc[l * 2 + 1];
                asm volatile(
                    "mma.sync.aligned.m16n8k16.row.col.f32.f16.f16.f32 "
                    "{%0,%1,%2,%3}, {%4,%5,%6,%7}, {%8,%9}, {%0,%1,%2,%3};"
                    : "+f"(c1[0]), "+f"(c1[1]), "+f"(c1[2]), "+f"(c1[3])
                    : "r"(a0), "r"(a1), "r"(a2), "r"(a3), "r"(b2), "r"(b3));
            }
        }
    }

    int rA = row0 + m0 + (lane >> 2);
    int rB = rA + 8;
    #pragma unroll
    for (int j = 0; j < 5; ++j) {
        int nn = j * 8 + (lane & 3) * 2;  // 0..39
        float bx = __ldg(&b[nn]), by = __ldg(&b[nn + 1]);
        int wofs = j * 4 + (lane & 3);    // word index 0..19
        if (rA < n) {
            __half2 h = __floats2half2_rn(acc[j][0] + bx, acc[j][1] + by);
            unsigned wv = *(unsigned*)&h;
            ((unsigned*)g_h2h)[rA * 20 + wofs] = wv;
            ((unsigned*)g_a2h)[rA * 20 + wofs] = wv;
        }
        if (rB < n) {
            __half2 h = __floats2half2_rn(acc[j][2] + bx, acc[j][3] + by);
            unsigned wv = *(unsigned*)&h;
            ((unsigned*)g_h2h)[rB * 20 + wofs] = wv;
            ((unsigned*)g_a2h)[rB * 20 + wofs] = wv;
        }
    }
}

// ====== scatter2: agg2[dst] += h2[src], ILP-4, warp-aligned ==========
// 24 edges/warp: lanes 0-29 in 6 groups of 5; each group: e0,+6,+12,+18.
__global__ __launch_bounds__(256) void k_scatter2(const void* __restrict__ ei, int E) {
    int t = blockIdx.x * blockDim.x + threadIdx.x;
    int warpid = t >> 5;
    int lane = t & 31;
    if (lane >= 30) return;
    int grp = lane / 5, sub = lane - grp * 5;
    int eb = warpid * 24 + grp;
    if (eb >= E) return;

    int s[4], d[4];
    bool ok[4];
    #pragma unroll
    for (int j = 0; j < 4; ++j) {
        int e = eb + j * 6;
        ok[j] = (e < E);
    }
    if (g_is64) {
        const long long* p = (const long long*)ei;
        #pragma unroll
        for (int j = 0; j < 4; ++j) if (ok[j]) {
            int e = eb + j * 6;
            s[j] = (int)__ldg(&p[e]); d[j] = (int)__ldg(&p[E + e]);
        }
    } else {
        const int* p = (const int*)ei;
        #pragma unroll
        for (int j = 0; j < 4; ++j) if (ok[j]) {
            int e = eb + j * 6;
            s[j] = __ldg(&p[e]); d[j] = __ldg(&p[E + e]);
        }
    }
    uint4 v[4];
    #pragma unroll
    for (int j = 0; j < 4; ++j) if (ok[j])
        v[j] = __ldg(&g_h2h[s[j] * 5 + sub]);
    #pragma unroll
    for (int j = 0; j < 4; ++j) if (ok[j])
        asm volatile("red.global.add.noftz.v4.f16x2 [%0], {%1,%2,%3,%4};"
                     :: "l"(&g_a2h[d[j] * 5 + sub]),
                        "r"(v[j].x), "r"(v[j].y), "r"(v[j].z), "r"(v[j].w) : "memory");
}

// ====== finalize: out = log_softmax(agg2/(deg+1))  (warp/row) =========
__global__ __launch_bounds__(256) void k_finalize(float* __restrict__ out, int n) {
    int row  = (blockIdx.x * blockDim.x + threadIdx.x) >> 5;
    int lane = threadIdx.x & 31;
    if (row >= n) return;
    float x0 = -3.4e38f, x1 = -3.4e38f;
    float iv = 1.0f / (float)(g_deg[row] + 1);
    if (lane < 20) {
        unsigned w = ((const unsigned*)g_a2h)[row * 20 + lane];
        float2 f = __half22float2(*(__half2*)&w);
        x0 = f.x * iv; x1 = f.y * iv;
    }
    float m = fmaxf(x0, x1);
    #pragma unroll
    for (int o = 16; o > 0; o >>= 1)
        m = fmaxf(m, __shfl_xor_sync(0xFFFFFFFFu, m, o));
    float s = (lane < 20) ? (expf(x0 - m) + expf(x1 - m)) : 0.f;
    #pragma unroll
    for (int o = 16; o > 0; o >>= 1)
        s += __shfl_xor_sync(0xFFFFFFFFu, s, o);
    float l = m + logf(s);
    if (lane < 20) {
        float2 o2;
        o2.x = x0 - l; o2.y = x1 - l;
        ((float2*)(out + (size_t)row * NCLS))[lane] = o2;
    }
}

// ---------------- launch ----------------
extern "C" void kernel_launch(void* const* d_in, const int* in_sizes, int n_in,
                              void* d_out, int out_size)
{
    const float* x  = (const float*)d_in[0];
    const void*  ei = d_in[1];
    const float* W1 = (const float*)d_in[2];
    const float* b1 = (const float*)d_in[3];
    const float* W2 = (const float*)d_in[4];
    const float* b2 = (const float*)d_in[5];
    float* out = (float*)d_out;

    int n = in_sizes[0] / NFEAT;      // 100000
    int E = in_sizes[1] / 2;          // 1600000

    int w1 = (E + 15) / 16;           // scatter1 warps (16 edges/warp)
    int w2 = (E + 23) / 24;           // scatter2 warps (24 edges/warp)

    k_gemm1   <<<(n + 127) / 128, 256>>>(x, W1, b1, (const unsigned*)ei, n);
    k_scatter1<<<(w1 * 32 + 255) / 256, 256>>>(ei, E);
    k_gemm2   <<<(n + 127) / 128, 256>>>(W2, b2, n);
    k_scatter2<<<(w2 * 32 + 255) / 256, 256>>>(ei, E);
    k_finalize<<<(n + 7) / 8, 256>>>(out, n);
}